// round 15
// baseline (speedup 1.0000x reference)
#include <cuda_runtime.h>
#include <cuda_fp16.h>
#include <math.h>
#include <stdint.h>

#define NMAX 50000
#define EMAX 400000
#define GTE 64   // edges per gemm tile
#define HS 72    // half stride per row (A and B smem)

// ---- scratch (device globals; no allocation allowed) ----
__device__ float g_ref_accum[NMAX * 4];            // sum x,y,z + count
__device__ __half2 g_sproj_h[(size_t)NMAX * 96];   // fp16 node projections
__device__ uint4 g_geom_h4[EMAX];                  // fp16 geom (8 halves/edge)
__device__ uint4 g_rbf_h4[(size_t)EMAX * 8];       // fp16 rbf (64 halves/edge)
__device__ __half g_x[(size_t)EMAX * 192];         // gated messages (fp16)

// ---------------- helpers ----------------
typedef unsigned long long u64;
__device__ __forceinline__ u64 pk2(float lo, float hi) {
    u64 r;
    asm("mov.b64 %0, {%1, %2};" : "=l"(r) : "f"(lo), "f"(hi));
    return r;
}
__device__ __forceinline__ void upk2(u64 v, float& lo, float& hi) {
    asm("mov.b64 {%0, %1}, %2;" : "=f"(lo), "=f"(hi) : "l"(v));
}
__device__ __forceinline__ u64 ffma2(u64 a, u64 b, u64 c) {
    u64 d;
    asm("fma.rn.f32x2 %0, %1, %2, %3;" : "=l"(d) : "l"(a), "l"(b), "l"(c));
    return d;
}
__device__ __forceinline__ float tanh_fast(float x) {
    float y;
    asm("tanh.approx.f32 %0, %1;" : "=f"(y) : "f"(x));
    return y;
}
__device__ __forceinline__ void red4(float* a, float x, float y, float z, float w) {
    asm volatile("red.global.add.v4.f32 [%0], {%1, %2, %3, %4};"
                 :: "l"(a), "f"(x), "f"(y), "f"(z), "f"(w) : "memory");
}
__device__ __forceinline__ uint32_t f2h2(float a, float b) {
    __half2 h = __floats2half2_rn(a, b);
    return *(uint32_t*)&h;
}
__device__ __forceinline__ void cpa16(void* dst, const void* src) {
    uint32_t d = (uint32_t)__cvta_generic_to_shared(dst);
    asm volatile("cp.async.ca.shared.global [%0], [%1], 16;"
                 :: "r"(d), "l"(src));
}
__device__ __forceinline__ void mma_f16(float c[4], uint32_t a0, uint32_t a1,
                                        uint32_t a2, uint32_t a3,
                                        uint32_t b0, uint32_t b1) {
    asm volatile(
        "mma.sync.aligned.m16n8k16.row.col.f32.f16.f16.f32 "
        "{%0,%1,%2,%3}, {%4,%5,%6,%7}, {%8,%9}, {%0,%1,%2,%3};"
        : "+f"(c[0]), "+f"(c[1]), "+f"(c[2]), "+f"(c[3])
        : "r"(a0), "r"(a1), "r"(a2), "r"(a3), "r"(b0), "r"(b1));
}
__device__ __forceinline__ void mma_f16_k8(float c[4], uint32_t a0, uint32_t a1,
                                           uint32_t b0) {
    asm volatile(
        "mma.sync.aligned.m16n8k8.row.col.f32.f16.f16.f32 "
        "{%0,%1,%2,%3}, {%4,%5}, {%6}, {%0,%1,%2,%3};"
        : "+f"(c[0]), "+f"(c[1]), "+f"(c[2]), "+f"(c[3])
        : "r"(a0), "r"(a1), "r"(b0));
}
// gate = 1 + tanh(silu(g)/0.6); silu via sigmoid(g) = 0.5*(1+tanh(g/2))
__device__ __forceinline__ float gatef(float g) {
    float t = tanh_fast(g * 0.5f);
    float sg = g * (1.0f + t) * (0.5f / 0.6f);
    return 1.0f + tanh_fast(sg);
}

// ================= kernel 1: zero ref accumulators (small) =================
__global__ void k_zacc(int n_acc4) {
    float4* acc4 = (float4*)g_ref_accum;
    int i = blockIdx.x * blockDim.x + threadIdx.x;
    if (i < n_acc4) acc4[i] = make_float4(0.f, 0.f, 0.f, 0.f);
}

// ================= kernel 2: segment-sum of edge_udiff over i =================
__global__ void k_refaccum(const float* __restrict__ ud,
                           const int* __restrict__ eidx, int E) {
    int e = blockIdx.x * blockDim.x + threadIdx.x;
    if (e >= E) return;
    int i = eidx[E + e];
    red4(&g_ref_accum[i * 4], ud[e * 3 + 0], ud[e * 3 + 1], ud[e * 3 + 2], 1.0f);
}

// ================= spherical-harmonic invariants (streamed) =================
__device__ __forceinline__ void sh_invariants(
    float xe, float ye, float ze, float xr, float yr, float zr, float* inv) {
    float nne = rsqrtf(xe * xe + ye * ye + ze * ze + 1e-12f);
    xe *= nne; ye *= nne; ze *= nne;
    float nnr = rsqrtf(xr * xr + yr * yr + zr * zr + 1e-12f);
    xr *= nnr; yr *= nnr; zr *= nnr;
    float st2e = xe * xe + ye * ye;
    float st2r = xr * xr + yr * yr;
    float ste = sqrtf(st2e), str = sqrtf(st2r);
    float c1e = (st2e > 0.0f) ? xe / ste : 0.0f;
    float s1e = (st2e > 0.0f) ? ye / ste : 0.0f;
    float c1r = (st2r > 0.0f) ? xr / str : 0.0f;
    float s1r = (st2r > 0.0f) ? yr / str : 0.0f;

    float acc[7];
#pragma unroll
    for (int l = 0; l < 7; l++) acc[l] = 0.0f;

    float de = 0.28209479177387814f, dr = 0.28209479177387814f;
    float ce = 1.0f, se = 0.0f, cr = 1.0f, sr = 0.0f;
#pragma unroll
    for (int m = 0; m <= 6; m++) {
        if (m > 0) {
            float km = sqrtf((2.0f * m + 1.0f) / (2.0f * m));
            de = -km * ste * de;
            dr = -km * str * dr;
            float ce2 = c1e * ce - s1e * se; se = s1e * ce + c1e * se; ce = ce2;
            float cr2 = c1r * cr - s1r * sr; sr = s1r * cr + c1r * sr; cr = cr2;
        }
        float w = (m == 0) ? 1.0f : 2.0f * (ce * cr + se * sr);
        float pe1 = de, pr1 = dr;
        acc[m] += w * pe1 * pr1;
        if (m < 6) {
            float kp = sqrtf(2.0f * m + 3.0f);
            float pe = kp * ze * de;
            float pr = kp * zr * dr;
            acc[m + 1] += w * pe * pr;
            float pe0 = pe1, pr0 = pr1;
#pragma unroll
            for (int l = m + 2; l <= 6; l++) {
                float fl = (float)l;
                float a = sqrtf((4.0f * fl * fl - 1.0f) / (fl * fl - (float)(m * m)));
                float b = sqrtf(((fl - 1.0f) * (fl - 1.0f) - (float)(m * m)) /
                                (4.0f * (fl - 1.0f) * (fl - 1.0f) - 1.0f));
                float pen = a * (ze * pe - b * pe0); pe0 = pe; pe = pen;
                float prn = a * (zr * pr - b * pr0); pr0 = pr; pr = prn;
                acc[l] += w * pe * pr;
            }
        }
    }
    const float fourpi = 12.566370614359172f;
#pragma unroll
    for (int l = 0; l < 7; l++) inv[l] = acc[l] * (fourpi / (2.0f * l + 1.0f));
}

// ====== kernel 3: fused pre-work — roles by block range (all independent) ======
//   [0, GB)        geom (inline refvec + SH invariants, fp16 out)
//   [GB, +SB)      sproj (node MLP, fp16 out)
//   [.., +ZB)      zero d_out
//   [.., +RB)      rbf f32 -> fp16 conversion
#define GB 1563
#define SB 888
#define ZB 400
#define RB 1024

__global__ void __launch_bounds__(256)
k_pre(const float* __restrict__ ud, const int* __restrict__ eidx,
      const float* __restrict__ ln_g, const float* __restrict__ ln_b,
      const float* __restrict__ ns, const float* __restrict__ W1,
      const float* __restrict__ b1, const float* __restrict__ W2,
      const float* __restrict__ b2, const float* __restrict__ rbf,
      float4* __restrict__ out4, int n_out4, int N, int E) {
    __shared__ float sW1[64 * 32];
    __shared__ float sW2[32 * 192];
    int tid = threadIdx.x;
    int bid = blockIdx.x;

    if (bid < GB) {
        // ---------------- geom role ----------------
        int e = bid * 256 + tid;
        if (e >= E) return;
        float ux = ud[e * 3 + 0], uy = ud[e * 3 + 1], uz = ud[e * 3 + 2];
        int i = __ldg(&eidx[E + e]);
        float4 a = *(const float4*)&g_ref_accum[i * 4];
        float ic = 1.0f / fmaxf(a.w, 1.0f);
        float rx = a.x * ic, ry = a.y * ic, rz = a.z * ic;
        float norm = sqrtf(rx * rx + ry * ry + rz * rz + 1e-9f);
        float inm = 1.0f / norm;
        rx *= inm; ry *= inm; rz *= inm;
        if (norm < 5e-5f) { rx = 1.0f; ry = 0.0f; rz = 0.0f; }

        float inv[7];
        sh_invariants(ux, uy, uz, rx, ry, rz, inv);
        float mu = 0.0f;
#pragma unroll
        for (int l = 0; l < 7; l++) mu += inv[l];
        mu *= (1.0f / 7.0f);
        float var = 0.0f;
#pragma unroll
        for (int l = 0; l < 7; l++) { float d = inv[l] - mu; var += d * d; }
        var *= (1.0f / 7.0f);
        float isd = rsqrtf(var + 1e-5f);
        float o[8];
        o[0] = ux * rx + uy * ry + uz * rz;
#pragma unroll
        for (int l = 0; l < 7; l++)
            o[1 + l] = (inv[l] - mu) * isd * ln_g[l] + ln_b[l];
        uint4 u;
        u.x = f2h2(o[0], o[1]); u.y = f2h2(o[2], o[3]);
        u.z = f2h2(o[4], o[5]); u.w = f2h2(o[6], o[7]);
        g_geom_h4[e] = u;
        return;
    }
    if (bid >= GB + SB + ZB) {
        // ---------------- rbf fp16 conversion role ----------------
        int rb = bid - GB - SB - ZB;
        size_t total = (size_t)E * 8;  // uint4 chunks (8 halves each)
        for (size_t i = (size_t)rb * 256 + tid; i < total; i += (size_t)RB * 256) {
            const float4* src = (const float4*)(rbf + i * 8);
            float4 v0 = __ldg(src), v1 = __ldg(src + 1);
            uint4 u;
            u.x = f2h2(v0.x, v0.y); u.y = f2h2(v0.z, v0.w);
            u.z = f2h2(v1.x, v1.y); u.w = f2h2(v1.z, v1.w);
            g_rbf_h4[i] = u;
        }
        return;
    }
    if (bid >= GB + SB) {
        // ---------------- zero-out role ----------------
        int zb = bid - GB - SB;
        float4 z = make_float4(0.f, 0.f, 0.f, 0.f);
        for (int i = zb * 256 + tid; i < n_out4; i += ZB * 256) out4[i] = z;
        return;
    }

    // ---------------- sproj role (fp16 output) ----------------
    int sbid = bid - GB;
    for (int q = tid; q < 64 * 32; q += 256) sW1[q] = W1[q];
    for (int q = tid; q < 32 * 192; q += 256) sW2[q] = W2[q];
    __syncthreads();
    const u64* sW2u = (const u64*)sW2;
    const float2* b2p = (const float2*)b2;
    int lane = tid & 31, warp = tid >> 5;

    u64 bb[3];
#pragma unroll
    for (int k = 0; k < 3; k++) {
        float2 t = b2p[lane + 32 * k];
        bb[k] = pk2(t.x, t.y);
    }
    float b1v = b1[lane];

    int npairs = (N + 1) >> 1;
    for (int p = sbid * 8 + warp; p < npairs; p += SB * 8) {
        int nA = p * 2;
        int nB = min(nA + 1, N - 1);
        float aA0 = ns[(size_t)nA * 64 + lane], aA1 = ns[(size_t)nA * 64 + 32 + lane];
        float aB0 = ns[(size_t)nB * 64 + lane], aB1 = ns[(size_t)nB * 64 + 32 + lane];
        float tA = b1v, tB = b1v;
#pragma unroll
        for (int r = 0; r < 64; r++) {
            float w = sW1[r * 32 + lane];
            float vA = __shfl_sync(0xffffffffu, (r < 32) ? aA0 : aA1, r & 31);
            float vB = __shfl_sync(0xffffffffu, (r < 32) ? aB0 : aB1, r & 31);
            tA = fmaf(vA, w, tA);
            tB = fmaf(vB, w, tB);
        }
        tA = __fdividef(tA, 1.0f + __expf(-tA)) * (1.0f / 0.6f);
        tB = __fdividef(tB, 1.0f + __expf(-tB)) * (1.0f / 0.6f);
        u64 oA[3], oB[3];
#pragma unroll
        for (int k = 0; k < 3; k++) { oA[k] = bb[k]; oB[k] = bb[k]; }
#pragma unroll
        for (int r = 0; r < 32; r++) {
            u64 w0 = sW2u[r * 96 + lane];
            u64 w1 = sW2u[r * 96 + 32 + lane];
            u64 w2 = sW2u[r * 96 + 64 + lane];
            float vA = __shfl_sync(0xffffffffu, tA, r);
            float vB = __shfl_sync(0xffffffffu, tB, r);
            u64 vvA = pk2(vA, vA), vvB = pk2(vB, vB);
            oA[0] = ffma2(vvA, w0, oA[0]);
            oA[1] = ffma2(vvA, w1, oA[1]);
            oA[2] = ffma2(vvA, w2, oA[2]);
            oB[0] = ffma2(vvB, w0, oB[0]);
            oB[1] = ffma2(vvB, w1, oB[1]);
            oB[2] = ffma2(vvB, w2, oB[2]);
        }
        __half2* outA = g_sproj_h + (size_t)nA * 96;
#pragma unroll
        for (int k = 0; k < 3; k++) {
            float lo, hi; upk2(oA[k], lo, hi);
            outA[lane + 32 * k] = __floats2half2_rn(lo, hi);
        }
        if (nB != nA) {
            __half2* outB = g_sproj_h + (size_t)nB * 96;
#pragma unroll
            for (int k = 0; k < 3; k++) {
                float lo, hi; upk2(oB[k], lo, hi);
                outB[lane + 32 * k] = __floats2half2_rn(lo, hi);
            }
        }
    }
}

// ====== kernel 4: fp16 MMA GEMM + tensor gate, cp.async double-buffered ======
// Persistent CTAs (3/SM), 256 threads = 8 warps (4 m-warps x 2 n-warps).
__global__ void __launch_bounds__(256, 3)
k_gemm(const int* __restrict__ eidx, const float* __restrict__ b_edge,
       const float* __restrict__ W_edge, const float* __restrict__ W_inv,
       const float* __restrict__ b_inv, int E) {
    extern __shared__ float sm[];
    __half* sBh  = (__half*)sm;             // 192*HS (W_edge^T, k contig)
    __half* sAh  = sBh + 192 * HS;          // 2 x 64*HS (rbf tiles, dbl buf)
    __half* sGh  = sAh + 2 * 64 * HS;       // 2 x 64*8 (geom tiles)
    __half* sWih = sGh + 2 * 64 * 8;        // 192*8 (W_inv)
    float* sBe = (float*)(sWih + 192 * 8);  // 192
    float* sBi = sBe + 192;                 // 192
    int*   sJ  = (int*)(sBi + 192);         // 2 x 64

    int tid = threadIdx.x;
    int lane = tid & 31, warp = tid >> 5;
    int wm = warp >> 1, wn = warp & 1;
    int gid = lane >> 2, tig = lane & 3;

    // persistent staging: W_edge^T (fp16), W_inv (fp16), biases
    for (int i = tid; i < 64 * 192; i += 256) {
        int k = i / 192, n = i - k * 192;
        sBh[n * HS + k] = __float2half_rn(W_edge[i]);
    }
    for (int i = tid; i < 8 * 192; i += 256) {
        int q = i / 192, n = i - q * 192;
        sWih[n * 8 + q] = __float2half_rn(W_inv[i]);
    }
    if (tid < 192) { sBe[tid] = b_edge[tid]; sBi[tid] = b_inv[tid]; }

    const float2* sBe2 = (const float2*)sBe;
    const float2* sBi2 = (const float2*)sBi;

    int r0 = wm * 16 + gid;
    int nb_base = wn * 96;
    const float inv_sqrt3 = 0.57735026918962576f;
    int ntiles = (E + GTE - 1) / GTE;

    // ---- staging helper (inlined via lambda-style macro) ----
#define STAGE_TILE(T, BUF)                                                    \
    do {                                                                      \
        int _e0 = (T) * GTE;                                                  \
        if (_e0 + GTE <= E) {                                                 \
            for (int _i = tid; _i < 512; _i += 256) {                         \
                int _r = _i >> 3, _c = _i & 7;                                \
                cpa16(sAh + (BUF) * 64 * HS + _r * HS + _c * 8,               \
                      &g_rbf_h4[(size_t)(_e0 + _r) * 8 + _c]);                \
            }                                                                 \
            if (tid < 64)                                                     \
                cpa16(sGh + (BUF) * 512 + tid * 8, &g_geom_h4[_e0 + tid]);    \
            else if (tid < 80)                                                \
                cpa16(sJ + (BUF) * 64 + (tid - 64) * 4,                       \
                      eidx + _e0 + (tid - 64) * 4);                           \
        } else {                                                              \
            for (int _i = tid; _i < 512; _i += 256) {                         \
                int _r = _i >> 3, _c = _i & 7;                                \
                int _e = min(_e0 + _r, E - 1);                                \
                *(uint4*)(sAh + (BUF) * 64 * HS + _r * HS + _c * 8) =         \
                    g_rbf_h4[(size_t)_e * 8 + _c];                            \
            }                                                                 \
            if (tid < 64) {                                                   \
                int _e = min(_e0 + tid, E - 1);                               \
                *(uint4*)(sGh + (BUF) * 512 + tid * 8) = g_geom_h4[_e];       \
                sJ[(BUF) * 64 + tid] = eidx[_e];                              \
            }                                                                 \
        }                                                                     \
    } while (0)

    int t = blockIdx.x;
    if (t < ntiles) STAGE_TILE(t, 0);
    asm volatile("cp.async.commit_group;");
    int pb = 0;

    for (; t < ntiles; t += gridDim.x) {
        int nt = t + gridDim.x;
        if (nt < ntiles) STAGE_TILE(nt, pb ^ 1);
        asm volatile("cp.async.commit_group;");
        asm volatile("cp.async.wait_group 1;");
        __syncthreads();

        int e0 = t * GTE;
        const __half* sA = sAh + pb * 64 * HS;
        const __half* sG = sGh + pb * 512;
        const int* sJp = sJ + pb * 64;

        int j0 = sJp[r0], j1 = sJp[r0 + 8];
        bool val0 = (e0 + r0) < E, val1 = (e0 + r0 + 8) < E;
        __half* xrow0 = g_x + (size_t)(e0 + r0) * 192;
        __half* xrow1 = g_x + (size_t)(e0 + r0 + 8) * 192;

        uint32_t ga0 = *(const uint32_t*)(sG + r0 * 8 + tig * 2);
        uint32_t ga1 = *(const uint32_t*)(sG + (r0 + 8) * 8 + tig * 2);

#pragma unroll
        for (int h = 0; h < 2; h++) {
            int nbh = nb_base + h * 48;
            float acc[6][4];
            __half2 gate[6][2];

            // ---- gate MMA (k8) ----
#pragma unroll
            for (int nb = 0; nb < 6; nb++)
                acc[nb][0] = acc[nb][1] = acc[nb][2] = acc[nb][3] = 0.0f;
#pragma unroll
            for (int nb = 0; nb < 6; nb++) {
                int n = nbh + nb * 8 + gid;
                uint32_t b0 = *(const uint32_t*)(sWih + n * 8 + tig * 2);
                mma_f16_k8(acc[nb], ga0, ga1, b0);
            }
#pragma unroll
            for (int nb = 0; nb < 6; nb++) {
                int ch = (nbh + nb * 8 + tig * 2) >> 1;
                float2 bi = sBi2[ch];
                gate[nb][0] = __floats2half2_rn(gatef(acc[nb][0] + bi.x),
                                                gatef(acc[nb][1] + bi.y));
                gate[nb][1] = __floats2half2_rn(gatef(acc[nb][2] + bi.x),
                                                gatef(acc[nb][3] + bi.y));
                acc[nb][0] = acc[nb][1] = acc[nb][2] = acc[nb][3] = 0.0f;
            }

            // ---- main MMA (4 k16-chunks) ----
#pragma unroll
            for (int kc = 0; kc < 4; kc++) {
                int kb = kc * 16 + tig * 2;
                uint32_t a0 = *(const uint32_t*)(sA + r0 * HS + kb);
                uint32_t a1 = *(const uint32_t*)(sA + (r0 + 8) * HS + kb);
                uint32_t a2 = *(const uint32_t*)(sA + r0 * HS + kb + 8);
                uint32_t a3 = *(const uint32_t*)(sA + (r0 + 8) * HS + kb + 8);
#pragma unroll
                for (int nb = 0; nb < 6; nb++) {
                    int n = nbh + nb * 8 + gid;
                    uint32_t b0 = *(const uint32_t*)(sBh + n * HS + kb);
                    uint32_t b1 = *(const uint32_t*)(sBh + n * HS + kb + 8);
                    mma_f16(acc[nb], a0, a1, a2, a3, b0, b1);
                }
            }

            // ---- epilogue: bias + gate + sproj -> g_x ----
#pragma unroll
            for (int nb = 0; nb < 6; nb++) {
                int col = nbh + nb * 8 + tig * 2;
                int ch = col >> 1;
                float2 be = sBe2[ch];
                float2 g0 = __half22float2(gate[nb][0]);
                float2 g1 = __half22float2(gate[nb][1]);
                float2 sp0 = __half22float2(__ldg(&g_sproj_h[(size_t)j0 * 96 + ch]));
                float2 sp1 = __half22float2(__ldg(&g_sproj_h[(size_t)j1 * 96 + ch]));
                float x00 = sp0.x * (acc[nb][0] + be.x) * g0.x * inv_sqrt3;
                float x01 = sp0.y * (acc[nb][1] + be.y) * g0.y * inv_sqrt3;
                float x10 = sp1.x * (acc[nb][2] + be.x) * g1.x * inv_sqrt3;
                float x11 = sp1.y * (acc[nb][3] + be.y) * g1.y * inv_sqrt3;
                if (val0) *(__half2*)(xrow0 + col) = __floats2half2_rn(x00, x01);
                if (val1) *(__half2*)(xrow1 + col) = __floats2half2_rn(x10, x11);
            }
        }
        __syncthreads();  // all reads of buf pb done before it is re-staged
        pb ^= 1;
    }
#undef STAGE_TILE
}

// ================= kernel 5: scatter (warp per edge) =================
__global__ void __launch_bounds__(256)
k_scatter(const float* __restrict__ ud, const int* __restrict__ eidx,
          const float* __restrict__ nv, float* __restrict__ out, int N, int E) {
    __shared__ __align__(16) float sX[8][192];
    int lane = threadIdx.x & 31, warp = threadIdx.x >> 5;
    float* xf = sX[warp];
    float* outv = out + (size_t)N * 64;
    const float ish = 0.125f;

    for (int e = blockIdx.x * 8 + warp; e < E; e += gridDim.x * 8) {
        const __half2* xr = (const __half2*)(g_x + (size_t)e * 192);
        float2 v0 = __half22float2(__ldg(xr + lane));        // x1
        float2 v1 = __half22float2(__ldg(xr + 32 + lane));   // x2
        float2 v2 = __half22float2(__ldg(xr + 64 + lane));   // x3
        ((float2*)xf)[lane] = v0;
        ((float2*)xf)[32 + lane] = v1;
        ((float2*)xf)[64 + lane] = v2;
        int j = __ldg(&eidx[e]), in = __ldg(&eidx[E + e]);
        float ud0 = __ldg(&ud[e * 3 + 0]);
        float ud1 = __ldg(&ud[e * 3 + 1]);
        float ud2 = __ldg(&ud[e * 3 + 2]);
        __syncwarp();

        if (lane < 16) {  // delta_scalar: x3
            const float4 x3v = *(const float4*)&xf[128 + 4 * lane];
            red4(&out[(size_t)in * 64 + 4 * lane], x3v.x, x3v.y, x3v.z, x3v.w);
        }
        {  // delta_vector d=0,1
            int o = 4 * lane;
            float udd = (o >> 6) ? ud1 : ud0;
            int h = o & 63;
            const float4 f1 = *(const float4*)&xf[h];
            const float4 f2 = *(const float4*)&xf[64 + h];
            float4 nvv = __ldg((const float4*)(nv + (size_t)j * 192 + o));
            red4(&outv[(size_t)in * 192 + o],
                 (f1.x * nvv.x + f2.x * udd) * ish,
                 (f1.y * nvv.y + f2.y * udd) * ish,
                 (f1.z * nvv.z + f2.z * udd) * ish,
                 (f1.w * nvv.w + f2.w * udd) * ish);
        }
        if (lane < 16) {  // delta_vector d=2
            int o = 128 + 4 * lane;
            int h = 4 * lane;
            const float4 f1 = *(const float4*)&xf[h];
            const float4 f2 = *(const float4*)&xf[64 + h];
            float4 nvv = __ldg((const float4*)(nv + (size_t)j * 192 + o));
            red4(&outv[(size_t)in * 192 + o],
                 (f1.x * nvv.x + f2.x * ud2) * ish,
                 (f1.y * nvv.y + f2.y * ud2) * ish,
                 (f1.z * nvv.z + f2.z * ud2) * ish,
                 (f1.w * nvv.w + f2.w * ud2) * ish);
        }
        __syncwarp();
    }
}

// ================= launch =================
extern "C" void kernel_launch(void* const* d_in, const int* in_sizes, int n_in,
                              void* d_out, int out_size) {
    const float* node_scalar = (const float*)d_in[0];
    const float* node_vector = (const float*)d_in[1];
    const float* edge_rbf    = (const float*)d_in[2];
    const float* edge_udiff  = (const float*)d_in[3];
    const int*   edge_index  = (const int*)d_in[4];
    const float* W_edge      = (const float*)d_in[5];
    const float* b_edge      = (const float*)d_in[6];
    const float* W_x1        = (const float*)d_in[7];
    const float* b_x1        = (const float*)d_in[8];
    const float* W_x2        = (const float*)d_in[9];
    const float* b_x2        = (const float*)d_in[10];
    const float* ln_g        = (const float*)d_in[11];
    const float* ln_b        = (const float*)d_in[12];
    const float* W_inv       = (const float*)d_in[13];
    const float* b_inv       = (const float*)d_in[14];

    int N = in_sizes[0] / 64;
    int E = in_sizes[3] / 3;
    float* out = (float*)d_out;

    // smem: Bh + 2xAh + 2xGh + Wih (halves) + biases + 2xJ
    int smem_gemm = (192 * HS + 2 * 64 * HS + 2 * 64 * 8 + 192 * 8) * 2
                    + (192 + 192) * 4 + 2 * 64 * 4;
    cudaFuncSetAttribute(k_gemm, cudaFuncAttributeMaxDynamicSharedMemorySize,
                         smem_gemm);

    k_zacc<<<(N + 255) / 256, 256>>>(N);
    k_refaccum<<<(E + 255) / 256, 256>>>(edge_udiff, edge_index, E);
    // fused independent pre-work: geom + sproj + zero-out + rbf cvt
    k_pre<<<GB + SB + ZB + RB, 256>>>(edge_udiff, edge_index, ln_g, ln_b,
                                      node_scalar, W_x1, b_x1, W_x2, b_x2,
                                      edge_rbf, (float4*)out, out_size / 4, N, E);
    k_gemm<<<444, 256, smem_gemm>>>(edge_index, b_edge, W_edge, W_inv, b_inv, E);
    k_scatter<<<2960, 256>>>(edge_udiff, edge_index, node_vector, out, N, E);
}